// round 10
// baseline (speedup 1.0000x reference)
#include <cuda_runtime.h>

// out[i] = cos(x[i]) * cos(theta[i & 63])
// N = 33,554,432 fp32 -> 8,388,608 float4.
//
// FINAL kernel — converged at the DRAM roofline. Triple-confirmed best
// config: 45.12/45.15/45.18 us wall, 36.1-36.3 us kernel, 5.87-5.89 TB/s
// (74% of 8 TB/s spec = HBM3e mixed 1:1 read:write ceiling). SM-side is
// ~85% idle (issue ~15%, fma ~6%): every SM-side axis (MLP, block size,
// persistence, access width, cache hints, issue phasing) measured neutral.
// 268 MB of traffic is compulsory; L2 persistence is closed (carveout=0,
// device-limit changes forbidden by the harness).
//
// Config: 512-thread CTAs, 64B per thread, front-batched MLP=4 LDG.128,
// __cosf (MUFU) with an accurate-cosf shared theta table (64 entries).
// Per-thread inner stride = 512 float4 = 2048 floats == 0 mod 64, so each
// thread's theta vector is invariant across its 4 iterations.

#define THREADS 512
#define UNROLL  4
#define CHUNK   (THREADS * UNROLL)     // 2048 float4 per block

__global__ void __launch_bounds__(THREADS) qab_kernel(
    const float4* __restrict__ x4,
    const float* __restrict__ theta,
    float4* __restrict__ out4,
    int nvec)
{
    __shared__ float ct[64];
    if (threadIdx.x < 64) {
        ct[threadIdx.x] = cosf(theta[threadIdx.x]);   // accurate; 64 values
    }
    __syncthreads();

    const int base = blockIdx.x * CHUNK + threadIdx.x;
    const int t = (base << 2) & 63;                    // 16B-aligned theta slot
    const float4 c = *reinterpret_cast<const float4*>(&ct[t]);

    if (base + (UNROLL - 1) * THREADS < nvec) {
        // Front-batch all 4 LDG.128 (MLP=4)
        float4 v[UNROLL];
        #pragma unroll
        for (int k = 0; k < UNROLL; k++)
            v[k] = x4[base + k * THREADS];

        #pragma unroll
        for (int k = 0; k < UNROLL; k++) {
            float4 r;
            r.x = __cosf(v[k].x) * c.x;
            r.y = __cosf(v[k].y) * c.y;
            r.z = __cosf(v[k].z) * c.z;
            r.w = __cosf(v[k].w) * c.w;
            out4[base + k * THREADS] = r;
        }
    } else {
        // Tail path (unused for the shipped shape; kept for generality)
        #pragma unroll
        for (int k = 0; k < UNROLL; k++) {
            int i = base + k * THREADS;
            if (i < nvec) {
                float4 v = x4[i];
                float4 r;
                r.x = __cosf(v.x) * c.x;
                r.y = __cosf(v.y) * c.y;
                r.z = __cosf(v.z) * c.z;
                r.w = __cosf(v.w) * c.w;
                out4[i] = r;
            }
        }
    }
}

extern "C" void kernel_launch(void* const* d_in, const int* in_sizes, int n_in,
                              void* d_out, int out_size)
{
    const float* x     = (const float*)d_in[0];
    const float* theta = (const float*)d_in[1];
    float* out         = (float*)d_out;

    int n    = out_size;          // total elements (33,554,432)
    int nvec = n >> 2;            // float4 count (8,388,608)

    int blocks = (nvec + CHUNK - 1) / CHUNK;   // 4096 for the shipped shape

    qab_kernel<<<blocks, THREADS>>>(
        (const float4*)x, theta, (float4*)out, nvec);
}

// round 12
// speedup vs baseline: 1.0028x; 1.0028x over previous
#include <cuda_runtime.h>

// out[i] = cos(x[i]) * cos(theta[i & 63])
// N = 33,554,432 fp32 -> 8,388,608 float4.
//
// FINAL kernel — converged at the DRAM roofline. Quadruple-confirmed best
// config: 45.12/45.15/45.18/45.28 us wall, 36.1-36.7 us kernel,
// 5.80-5.89 TB/s (73-74.5% of 8 TB/s spec = HBM3e mixed 1:1 read:write
// ceiling, bus-turnaround limited). SM-side ~85% idle (issue ~15%, fma ~6%).
// Axes measured NEUTRAL: MLP 4/8, block 256/512, one-shot/persistent,
// 128/256-bit access, L2 eviction hints, issue phasing. Axes that WON:
// MLP 1->4 (+8us), cosf->__cosf + shared theta table (+7us).
// Closed levers: L2 persistence (carveout=0, device-limit changes forbidden),
// output narrowing (fp32 contract), input reuse (random data), TMA (same
// path-independent LTS cap).
//
// Config: 512-thread CTAs, 64B per thread, front-batched MLP=4 LDG.128,
// __cosf (MUFU) with accurate-cosf shared theta table (64 entries).
// Per-thread inner stride = 512 float4 = 2048 floats == 0 mod 64, so each
// thread's theta vector is invariant across its 4 iterations.

#define THREADS 512
#define UNROLL  4
#define CHUNK   (THREADS * UNROLL)     // 2048 float4 per block

__global__ void __launch_bounds__(THREADS) qab_kernel(
    const float4* __restrict__ x4,
    const float* __restrict__ theta,
    float4* __restrict__ out4,
    int nvec)
{
    __shared__ float ct[64];
    if (threadIdx.x < 64) {
        ct[threadIdx.x] = cosf(theta[threadIdx.x]);   // accurate; 64 values
    }
    __syncthreads();

    const int base = blockIdx.x * CHUNK + threadIdx.x;
    const int t = (base << 2) & 63;                    // 16B-aligned theta slot
    const float4 c = *reinterpret_cast<const float4*>(&ct[t]);

    if (base + (UNROLL - 1) * THREADS < nvec) {
        // Front-batch all 4 LDG.128 (MLP=4)
        float4 v[UNROLL];
        #pragma unroll
        for (int k = 0; k < UNROLL; k++)
            v[k] = x4[base + k * THREADS];

        #pragma unroll
        for (int k = 0; k < UNROLL; k++) {
            float4 r;
            r.x = __cosf(v[k].x) * c.x;
            r.y = __cosf(v[k].y) * c.y;
            r.z = __cosf(v[k].z) * c.z;
            r.w = __cosf(v[k].w) * c.w;
            out4[base + k * THREADS] = r;
        }
    } else {
        // Tail path (unused for the shipped shape; kept for generality)
        #pragma unroll
        for (int k = 0; k < UNROLL; k++) {
            int i = base + k * THREADS;
            if (i < nvec) {
                float4 v = x4[i];
                float4 r;
                r.x = __cosf(v.x) * c.x;
                r.y = __cosf(v.y) * c.y;
                r.z = __cosf(v.z) * c.z;
                r.w = __cosf(v.w) * c.w;
                out4[i] = r;
            }
        }
    }
}

extern "C" void kernel_launch(void* const* d_in, const int* in_sizes, int n_in,
                              void* d_out, int out_size)
{
    const float* x     = (const float*)d_in[0];
    const float* theta = (const float*)d_in[1];
    float* out         = (float*)d_out;

    int n    = out_size;          // total elements (33,554,432)
    int nvec = n >> 2;            // float4 count (8,388,608)

    int blocks = (nvec + CHUNK - 1) / CHUNK;   // 4096 for the shipped shape

    qab_kernel<<<blocks, THREADS>>>(
        (const float4*)x, theta, (float4*)out, nvec);
}

// round 13
// speedup vs baseline: 1.0035x; 1.0007x over previous
#include <cuda_runtime.h>

// out[i] = cos(x[i]) * cos(theta[i & 63])
// N = 33,554,432 fp32 -> 8,388,608 float4.
//
// Direction-phased variant of the converged-roofline kernel (best: 45.12us).
// The binder is DRAM bus turnaround on a fine-grained 1:1 read:write mix
// (~73% of unidirectional spec). This round: block-level phase barrier
// between the load phase (32KB read burst per CTA) and the store phase,
// coarsening same-direction DRAM burst lengths seen by the controller.
// Everything else identical to the quadruple-confirmed best config:
// 512-thread CTAs, 64B/thread, MLP=4 LDG.128, __cosf + shared theta table.
// Per-thread inner stride = 512 float4 = 2048 floats == 0 mod 64, so each
// thread's theta vector is invariant across its 4 iterations.

#define THREADS 512
#define UNROLL  4
#define CHUNK   (THREADS * UNROLL)     // 2048 float4 per block

__global__ void __launch_bounds__(THREADS) qab_kernel(
    const float4* __restrict__ x4,
    const float* __restrict__ theta,
    float4* __restrict__ out4,
    int nvec)
{
    __shared__ float ct[64];
    if (threadIdx.x < 64) {
        ct[threadIdx.x] = cosf(theta[threadIdx.x]);   // accurate; 64 values
    }
    __syncthreads();

    const int base = blockIdx.x * CHUNK + threadIdx.x;
    const int t = (base << 2) & 63;                    // 16B-aligned theta slot
    const float4 c = *reinterpret_cast<const float4*>(&ct[t]);

    if (base + (UNROLL - 1) * THREADS < nvec) {
        // Phase 1: whole-CTA read burst (4 LDG.128 per thread, MLP=4)
        float4 v[UNROLL];
        #pragma unroll
        for (int k = 0; k < UNROLL; k++)
            v[k] = x4[base + k * THREADS];

        // Direction-phase barrier: no store issues until the CTA's 32KB of
        // reads have completed -> coarser same-direction DRAM bursts.
        __syncthreads();

        // Phase 2: compute + whole-CTA write burst
        #pragma unroll
        for (int k = 0; k < UNROLL; k++) {
            float4 r;
            r.x = __cosf(v[k].x) * c.x;
            r.y = __cosf(v[k].y) * c.y;
            r.z = __cosf(v[k].z) * c.z;
            r.w = __cosf(v[k].w) * c.w;
            out4[base + k * THREADS] = r;
        }
    } else {
        // Tail path (unused for the shipped shape; kept for generality)
        __syncthreads();   // keep barrier count uniform across the block
        #pragma unroll
        for (int k = 0; k < UNROLL; k++) {
            int i = base + k * THREADS;
            if (i < nvec) {
                float4 v = x4[i];
                float4 r;
                r.x = __cosf(v.x) * c.x;
                r.y = __cosf(v.y) * c.y;
                r.z = __cosf(v.z) * c.z;
                r.w = __cosf(v.w) * c.w;
                out4[i] = r;
            }
        }
    }
}

extern "C" void kernel_launch(void* const* d_in, const int* in_sizes, int n_in,
                              void* d_out, int out_size)
{
    const float* x     = (const float*)d_in[0];
    const float* theta = (const float*)d_in[1];
    float* out         = (float*)d_out;

    int n    = out_size;          // total elements (33,554,432)
    int nvec = n >> 2;            // float4 count (8,388,608)

    int blocks = (nvec + CHUNK - 1) / CHUNK;   // 4096 for the shipped shape

    qab_kernel<<<blocks, THREADS>>>(
        (const float4*)x, theta, (float4*)out, nvec);
}